// round 5
// baseline (speedup 1.0000x reference)
#include <cuda_runtime.h>
#include <cstddef>
#include <cstdint>

// Single-pass decoupled-LOOKBACK scan for c_t = a_t * c_{t-1} + b_t, c_{-1}=0.
// input  : [B, T, 2*UNITS] fp32   (a = [:,:,:UNITS], b = [:,:,UNITS:])
// output : [B, T, UNITS]
//
// R5: replace serial decoupled chaining (R3/R4) with CUB-style lookback.
// Each block publishes its local aggregate (A_blk, C_blk) as soon as its
// local scan finishes (no waiting), then resolves its global prefix by
// walking predecessors backward, composing aggregates and stopping at the
// first published INCLUSIVE prefix. The 64-hop serial chain that capped R4
// at 66% DRAM becomes ~2-3 composition steps overlapped with streaming.
// Flag protocol per (row, lane): 0=empty, 1=aggregate ready, 2=inclusive
// ready; release stores / acquire loads give data-flag ordering.

#define T_C      2048
#define UNITS_C  2048
#define B_MAX    16

constexpr int LANES   = 32;
constexpr int SEGS    = 8;
constexpr int LSEG    = 4;                    // timesteps per thread
constexpr int CHUNK_T = SEGS * LSEG;          // 32
constexpr int CH      = T_C / CHUNK_T;        // 64 time chunks
constexpr int VG      = UNITS_C / (LANES*4);  // 16 vec-groups per batch row
constexpr int NROWS   = B_MAX * VG * CH;      // 16384 carry rows

__device__ float4   g_aggA[NROWS][LANES];     // block aggregate: multiplier
__device__ float4   g_aggC[NROWS][LANES];     // block aggregate: offset
__device__ float4   g_incl[NROWS][LANES];     // inclusive prefix (c at chunk end)
__device__ unsigned g_flag[NROWS][LANES];     // 0 empty / 1 agg / 2 inclusive

__global__ void reset_flags_kernel()
{
    int i = blockIdx.x * blockDim.x + threadIdx.x;   // NROWS*LANES
    ((unsigned*)g_flag)[i] = 0u;
}

__device__ __forceinline__ float4 f4_fma(float4 a, float4 x, float4 b)
{   // a*x + b
    float4 r;
    r.x = fmaf(a.x, x.x, b.x); r.y = fmaf(a.y, x.y, b.y);
    r.z = fmaf(a.z, x.z, b.z); r.w = fmaf(a.w, x.w, b.w);
    return r;
}
__device__ __forceinline__ float4 f4_mul(float4 a, float4 b)
{
    float4 r; r.x=a.x*b.x; r.y=a.y*b.y; r.z=a.z*b.z; r.w=a.w*b.w; return r;
}

__global__ void __launch_bounds__(256, 4)
tempo_scan_kernel(const float* __restrict__ in, float* __restrict__ out, int nbatch)
{
    const int lane = threadIdx.x & 31;
    const int seg  = threadIdx.x >> 5;

    // chunk index in the HIGH bits of blockIdx so chunk-0 blocks dispatch first
    const int gpb = nbatch * VG;
    const int p   = blockIdx.x / gpb;          // time chunk
    const int r   = blockIdx.x % gpb;
    const int g   = r / VG;                    // batch
    const int vg  = r % VG;                    // vec-group (32 float4 lanes)

    const int rowbase = g * VG + vg;           // (batch, vg) row id
    const int t0 = p * CHUNK_T + seg * LSEG;
    const size_t uf = (size_t)(vg * LANES + lane) * 4;   // unit offset (floats)

    constexpr int ROW  = 2 * UNITS_C;          // input row stride (floats)
    constexpr int RS4  = ROW / 4;              // float4 stride: 1024
    constexpr int OS4  = UNITS_C / 4;          // 512

    const float4* pa = (const float4*)(in + ((size_t)g * T_C + t0) * ROW + uf);
    const float4* pb = (const float4*)(in + ((size_t)g * T_C + t0) * ROW + UNITS_C + uf);
    float4*       po = (float4*)(out + ((size_t)g * T_C + t0) * UNITS_C + uf);

    // ---- phase 1: issue all loads immediately (this is ALL the HBM read) ----
    float4 A[LSEG], C[LSEG];
    #pragma unroll
    for (int i = 0; i < LSEG; ++i) {
        A[i] = __ldcs(pa + (size_t)i * RS4);
        C[i] = __ldcs(pb + (size_t)i * RS4);
    }

    // local scan with zero prefix: C[i] = c_local_i, A[i] = prod_{j<=i} a_j
    #pragma unroll
    for (int i = 1; i < LSEG; ++i) {
        C[i] = f4_fma(A[i], C[i-1], C[i]);
        A[i] = f4_mul(A[i], A[i-1]);
    }

    // ---- intra-block segment scan via smem ----
    __shared__ float4 sA[SEGS][LANES];
    __shared__ float4 sC[SEGS][LANES];
    __shared__ float4 sP[LANES];

    sA[seg][lane] = A[LSEG-1];
    sC[seg][lane] = C[LSEG-1];
    __syncthreads();

    // exclusive prefix over segments 0..seg-1:  (EA, EC)
    float4 EA = make_float4(1.f,1.f,1.f,1.f);
    float4 EC = make_float4(0.f,0.f,0.f,0.f);
    #pragma unroll
    for (int j = 0; j < SEGS-1; ++j) {
        if (j < seg) {
            float4 Aj = sA[j][lane], Cj = sC[j][lane];
            EC = f4_fma(Aj, EC, Cj);
            EA = f4_mul(Aj, EA);
        }
    }

    // Block aggregate (owned by seg SEGS-1): maps block-input c -> block-output c
    float4 Aagg, Cagg;
    if (seg == SEGS-1) {
        Aagg = f4_mul(A[LSEG-1], EA);
        Cagg = f4_fma(A[LSEG-1], EC, C[LSEG-1]);
        if (p < CH-1 && p > 0) {
            // publish AGGREGATE immediately -- no dependency on predecessors
            const int rcur = p * gpb + rowbase;   // row id = chunk-major
            g_aggA[rcur][lane] = Aagg;
            g_aggC[rcur][lane] = Cagg;
            asm volatile("st.global.release.gpu.b32 [%0], %1;"
                         :: "l"(&g_flag[rcur][lane]), "r"(1u) : "memory");
        }
    }

    // ---- lookback (warp 0): resolve global prefix into this block ----
    if (seg == 0) {
        float4 P = make_float4(0.f,0.f,0.f,0.f);
        if (p > 0) {
            // (LA, LC): composition of chunks (j, p-1]; prefix_p = LA*out_j + LC
            float4 LA = make_float4(1.f,1.f,1.f,1.f);
            float4 LC = make_float4(0.f,0.f,0.f,0.f);
            int j = p - 1;
            for (;;) {
                const int rj = j * gpb + rowbase;
                const unsigned* f = &g_flag[rj][lane];
                unsigned v;
                asm volatile("ld.global.acquire.gpu.b32 %0, [%1];"
                             : "=r"(v) : "l"(f) : "memory");
                while (v == 0u) {
                    __nanosleep(40);
                    asm volatile("ld.global.acquire.gpu.b32 %0, [%1];"
                                 : "=r"(v) : "l"(f) : "memory");
                }
                if (v == 2u) {              // inclusive prefix available
                    float4 Pj = g_incl[rj][lane];
                    P = f4_fma(LA, Pj, LC);
                    break;
                }
                // aggregate only: compose and keep walking back
                float4 Aj = g_aggA[rj][lane];
                float4 Cj = g_aggC[rj][lane];
                LC = f4_fma(LA, Cj, LC);
                LA = f4_mul(LA, Aj);
                if (--j < 0) { P = LC; break; }   // hit sequence start: c_in = 0
            }
        }
        sP[lane] = P;
    }
    __syncthreads();

    // full c-prefix at this thread's segment start
    const float4 P  = sP[lane];
    const float4 Pc = f4_fma(EA, P, EC);

    // ---- publish INCLUSIVE prefix (upgrades flag 1 -> 2) ----
    if (seg == SEGS-1 && p < CH-1) {
        const int rcur = p * gpb + rowbase;
        g_incl[rcur][lane] = f4_fma(Aagg, P, Cagg);
        asm volatile("st.global.release.gpu.b32 [%0], %1;"
                     :: "l"(&g_flag[rcur][lane]), "r"(2u) : "memory");
    }

    // ---- finalize + store outputs ----
    #pragma unroll
    for (int i = 0; i < LSEG; ++i) {
        float4 cf = f4_fma(A[i], Pc, C[i]);
        __stcs(po + (size_t)i * OS4, cf);
    }
}

extern "C" void kernel_launch(void* const* d_in, const int* in_sizes, int n_in,
                              void* d_out, int out_size)
{
    const float* in  = (const float*)d_in[0];
    float*       out = (float*)d_out;

    const int batch = in_sizes[0] / (T_C * 2 * UNITS_C);

    reset_flags_kernel<<<(NROWS * LANES) / 256, 256>>>();

    const int grid = CH * batch * VG;      // 16384 for B=16
    tempo_scan_kernel<<<grid, 256>>>(in, out, batch);
}

// round 6
// speedup vs baseline: 1.0376x; 1.0376x over previous
#include <cuda_runtime.h>
#include <cstddef>
#include <cstdint>

// Single-pass decoupled-LOOKBACK scan for c_t = a_t * c_{t-1} + b_t, c_{-1}=0.
// input  : [B, T, 2*UNITS] fp32   (a = [:,:,:UNITS], b = [:,:,UNITS:])
// output : [B, T, UNITS]
//
// R6 = R5 lookback protocol + R3 geometry + overlap fix:
//  * CHUNK_T=64 (LSEG=8): R3-R5 showed chunk size controls DRAM% (64 -> 77.6%,
//    32 -> 66-69%): big chunks give each block enough streaming work to hide
//    the prefix-resolve phase.
//  * warp 0 runs the lookback walk IMMEDIATELY after issuing its loads, so
//    the spin overlaps the block's own in-flight HBM loads instead of running
//    after __syncthreads when all loads have already landed (R5 defect).
//  * aggregates are published without waiting on predecessors -> no serial
//    chain (R3/R4 defect).
// Flag protocol per (row, lane): 0=empty, 1=aggregate ready, 2=inclusive ready.

#define T_C      2048
#define UNITS_C  2048
#define B_MAX    16

constexpr int LANES   = 32;
constexpr int SEGS    = 8;
constexpr int LSEG    = 8;                    // timesteps per thread
constexpr int CHUNK_T = SEGS * LSEG;          // 64
constexpr int CH      = T_C / CHUNK_T;        // 32 time chunks
constexpr int VG      = UNITS_C / (LANES*4);  // 16 vec-groups per batch row
constexpr int NROWS   = B_MAX * VG * CH;      // 8192 carry rows

__device__ float4   g_aggA[NROWS][LANES];     // block aggregate: multiplier
__device__ float4   g_aggC[NROWS][LANES];     // block aggregate: offset
__device__ float4   g_incl[NROWS][LANES];     // inclusive prefix (c at chunk end)
__device__ unsigned g_flag[NROWS][LANES];     // 0 empty / 1 agg / 2 inclusive

__global__ void reset_flags_kernel()
{
    int i = blockIdx.x * blockDim.x + threadIdx.x;   // NROWS*LANES
    ((unsigned*)g_flag)[i] = 0u;
}

__device__ __forceinline__ float4 f4_fma(float4 a, float4 x, float4 b)
{   // a*x + b
    float4 r;
    r.x = fmaf(a.x, x.x, b.x); r.y = fmaf(a.y, x.y, b.y);
    r.z = fmaf(a.z, x.z, b.z); r.w = fmaf(a.w, x.w, b.w);
    return r;
}
__device__ __forceinline__ float4 f4_mul(float4 a, float4 b)
{
    float4 r; r.x=a.x*b.x; r.y=a.y*b.y; r.z=a.z*b.z; r.w=a.w*b.w; return r;
}

__global__ void __launch_bounds__(256, 2)
tempo_scan_kernel(const float* __restrict__ in, float* __restrict__ out, int nbatch)
{
    const int lane = threadIdx.x & 31;
    const int seg  = threadIdx.x >> 5;

    // chunk index in the HIGH bits of blockIdx so chunk-0 blocks dispatch first
    const int gpb = nbatch * VG;
    const int p   = blockIdx.x / gpb;          // time chunk
    const int r   = blockIdx.x % gpb;
    const int g   = r / VG;                    // batch
    const int vg  = r % VG;                    // vec-group (32 float4 lanes)

    const int rowbase = g * VG + vg;           // (batch, vg) row id
    const int t0 = p * CHUNK_T + seg * LSEG;
    const size_t uf = (size_t)(vg * LANES + lane) * 4;   // unit offset (floats)

    constexpr int ROW  = 2 * UNITS_C;          // input row stride (floats)
    constexpr int RS4  = ROW / 4;              // float4 stride: 1024
    constexpr int OS4  = UNITS_C / 4;          // 512

    const float4* pa = (const float4*)(in + ((size_t)g * T_C + t0) * ROW + uf);
    const float4* pb = (const float4*)(in + ((size_t)g * T_C + t0) * ROW + UNITS_C + uf);
    float4*       po = (float4*)(out + ((size_t)g * T_C + t0) * UNITS_C + uf);

    __shared__ float4 sA[SEGS][LANES];
    __shared__ float4 sC[SEGS][LANES];
    __shared__ float4 sP[LANES];

    // ---- phase 1: issue all loads immediately (this is ALL the HBM read) ----
    float4 A[LSEG], C[LSEG];
    #pragma unroll
    for (int i = 0; i < LSEG; ++i) {
        A[i] = __ldcs(pa + (size_t)i * RS4);
        C[i] = __ldcs(pb + (size_t)i * RS4);
    }

    // ---- warp 0: lookback walk NOW, overlapped with in-flight loads ----
    if (seg == 0) {
        float4 P = make_float4(0.f,0.f,0.f,0.f);
        if (p > 0) {
            // (LA, LC): composition of chunks (j, p-1]; prefix_p = LA*out_j + LC
            float4 LA = make_float4(1.f,1.f,1.f,1.f);
            float4 LC = make_float4(0.f,0.f,0.f,0.f);
            int j = p - 1;
            for (;;) {
                const int rj = j * gpb + rowbase;
                const unsigned* f = &g_flag[rj][lane];
                unsigned v;
                asm volatile("ld.global.acquire.gpu.b32 %0, [%1];"
                             : "=r"(v) : "l"(f) : "memory");
                while (v == 0u) {
                    __nanosleep(40);
                    asm volatile("ld.global.acquire.gpu.b32 %0, [%1];"
                                 : "=r"(v) : "l"(f) : "memory");
                }
                if (v == 2u) {              // inclusive prefix available
                    float4 Pj = g_incl[rj][lane];
                    P = f4_fma(LA, Pj, LC);
                    break;
                }
                // aggregate only: compose and keep walking back
                float4 Aj = g_aggA[rj][lane];
                float4 Cj = g_aggC[rj][lane];
                LC = f4_fma(LA, Cj, LC);
                LA = f4_mul(LA, Aj);
                if (--j < 0) { P = LC; break; }   // sequence start: c_in = 0
            }
        }
        sP[lane] = P;
    }

    // local scan with zero prefix: C[i] = c_local_i, A[i] = prod_{j<=i} a_j
    #pragma unroll
    for (int i = 1; i < LSEG; ++i) {
        C[i] = f4_fma(A[i], C[i-1], C[i]);
        A[i] = f4_mul(A[i], A[i-1]);
    }

    sA[seg][lane] = A[LSEG-1];
    sC[seg][lane] = C[LSEG-1];
    __syncthreads();

    // exclusive prefix over segments 0..seg-1:  (EA, EC)
    float4 EA = make_float4(1.f,1.f,1.f,1.f);
    float4 EC = make_float4(0.f,0.f,0.f,0.f);
    #pragma unroll
    for (int j = 0; j < SEGS-1; ++j) {
        if (j < seg) {
            float4 Aj = sA[j][lane], Cj = sC[j][lane];
            EC = f4_fma(Aj, EC, Cj);
            EA = f4_mul(Aj, EA);
        }
    }

    // Block aggregate (owned by seg SEGS-1): maps block-input c -> block-output c
    float4 Aagg, Cagg;
    if (seg == SEGS-1) {
        Aagg = f4_mul(A[LSEG-1], EA);
        Cagg = f4_fma(A[LSEG-1], EC, C[LSEG-1]);
        if (p < CH-1 && p > 0) {
            // publish AGGREGATE immediately -- no dependency on predecessors
            const int rcur = p * gpb + rowbase;
            g_aggA[rcur][lane] = Aagg;
            g_aggC[rcur][lane] = Cagg;
            asm volatile("st.global.release.gpu.b32 [%0], %1;"
                         :: "l"(&g_flag[rcur][lane]), "r"(1u) : "memory");
        }
    }

    // full c-prefix at this thread's segment start (sP written by warp 0
    // before the __syncthreads above for every path)
    const float4 P  = sP[lane];
    const float4 Pc = f4_fma(EA, P, EC);

    // ---- publish INCLUSIVE prefix (upgrades flag 1 -> 2) ----
    if (seg == SEGS-1 && p < CH-1) {
        const int rcur = p * gpb + rowbase;
        g_incl[rcur][lane] = f4_fma(Aagg, P, Cagg);
        asm volatile("st.global.release.gpu.b32 [%0], %1;"
                     :: "l"(&g_flag[rcur][lane]), "r"(2u) : "memory");
    }

    // ---- finalize + store outputs ----
    #pragma unroll
    for (int i = 0; i < LSEG; ++i) {
        float4 cf = f4_fma(A[i], Pc, C[i]);
        __stcs(po + (size_t)i * OS4, cf);
    }
}

extern "C" void kernel_launch(void* const* d_in, const int* in_sizes, int n_in,
                              void* d_out, int out_size)
{
    const float* in  = (const float*)d_in[0];
    float*       out = (float*)d_out;

    const int batch = in_sizes[0] / (T_C * 2 * UNITS_C);

    reset_flags_kernel<<<(NROWS * LANES) / 256, 256>>>();

    const int grid = CH * batch * VG;      // 8192 for B=16
    tempo_scan_kernel<<<grid, 256>>>(in, out, batch);
}

// round 7
// speedup vs baseline: 1.1294x; 1.0885x over previous
#include <cuda_runtime.h>
#include <cstddef>
#include <cstdint>

// Single-pass decoupled-chaining scan for c_t = a_t * c_{t-1} + b_t, c_{-1}=0.
// input  : [B, T, 2*UNITS] fp32   (a = [:,:,:UNITS], b = [:,:,UNITS:])
// output : [B, T, UNITS]
//
// R7 = R3 kernel (best measured: 124.5us = ~98% of the ~6.3TB/s LTS chip cap,
// the true ceiling for this 768MB stream) + CONSUMER-RESET flags:
// each flag has exactly one consumer (chunk p+1 reads chunk p); after the
// consumer acquires the flag and reads the carry it stores the flag back to 0.
// The "all flags 0 at launch start" invariant therefore self-maintains across
// graph replays (kernel-boundary ordering separates launch N's resets from
// launch N+1's producers), eliminating the reset prologue kernel whose graph
// node cost ~5.5us of the 130us total.

#define T_C      2048
#define UNITS_C  2048
#define B_MAX    16

constexpr int LANES   = 32;
constexpr int SEGS    = 8;
constexpr int LSEG    = 8;                    // timesteps per thread
constexpr int CHUNK_T = SEGS * LSEG;          // 64
constexpr int CH      = T_C / CHUNK_T;        // 32
constexpr int VG      = UNITS_C / (LANES*4);  // 16 vec-groups per batch row
constexpr int NROWS   = B_MAX * VG * CH;      // 8192 carry rows

__device__ float4   g_prefix[NROWS][LANES];
__device__ unsigned g_flag  [NROWS][LANES];   // zero-init at load; self-resetting

__device__ __forceinline__ float4 f4_fma(float4 a, float4 x, float4 b)
{   // a*x + b
    float4 r;
    r.x = fmaf(a.x, x.x, b.x); r.y = fmaf(a.y, x.y, b.y);
    r.z = fmaf(a.z, x.z, b.z); r.w = fmaf(a.w, x.w, b.w);
    return r;
}
__device__ __forceinline__ float4 f4_mul(float4 a, float4 b)
{
    float4 r; r.x=a.x*b.x; r.y=a.y*b.y; r.z=a.z*b.z; r.w=a.w*b.w; return r;
}

__global__ void __launch_bounds__(256, 2)
tempo_scan_kernel(const float* __restrict__ in, float* __restrict__ out, int nbatch)
{
    const int lane = threadIdx.x & 31;
    const int seg  = threadIdx.x >> 5;

    // chunk index in the HIGH bits of blockIdx so chunk-0 blocks dispatch first
    const int gpb = nbatch * VG;
    const int p   = blockIdx.x / gpb;          // time chunk
    const int r   = blockIdx.x % gpb;
    const int g   = r / VG;                    // batch
    const int vg  = r % VG;                    // vec-group (32 float4 lanes)

    const int t0 = p * CHUNK_T + seg * LSEG;
    const size_t uf = (size_t)(vg * LANES + lane) * 4;   // unit offset (floats)

    constexpr int ROW  = 2 * UNITS_C;          // input row stride (floats)
    constexpr int RS4  = ROW / 4;              // float4 stride: 1024
    constexpr int OS4  = UNITS_C / 4;          // 512

    const float4* pa = (const float4*)(in + ((size_t)g * T_C + t0) * ROW + uf);
    const float4* pb = (const float4*)(in + ((size_t)g * T_C + t0) * ROW + UNITS_C + uf);
    float4*       po = (float4*)(out + ((size_t)g * T_C + t0) * UNITS_C + uf);

    // ---- phase 1: issue all loads immediately (this is ALL the HBM read) ----
    float4 A[LSEG], C[LSEG];
    #pragma unroll
    for (int i = 0; i < LSEG; ++i) {
        A[i] = __ldcs(pa + (size_t)i * RS4);
        C[i] = __ldcs(pb + (size_t)i * RS4);
    }

    // local scan with zero prefix: C[i] = c_local_i, A[i] = prod_{j<=i} a_j
    #pragma unroll
    for (int i = 1; i < LSEG; ++i) {
        C[i] = f4_fma(A[i], C[i-1], C[i]);
        A[i] = f4_mul(A[i], A[i-1]);
    }

    // ---- intra-block segment scan via smem ----
    __shared__ float4 sA[SEGS][LANES];
    __shared__ float4 sC[SEGS][LANES];
    __shared__ float4 sP[LANES];

    sA[seg][lane] = A[LSEG-1];
    sC[seg][lane] = C[LSEG-1];
    __syncthreads();

    // exclusive prefix over segments 0..seg-1:  (EA, EC)
    float4 EA = make_float4(1.f,1.f,1.f,1.f);
    float4 EC = make_float4(0.f,0.f,0.f,0.f);
    #pragma unroll
    for (int j = 0; j < SEGS-1; ++j) {
        if (j < seg) {
            float4 Aj = sA[j][lane], Cj = sC[j][lane];
            EC = f4_fma(Aj, EC, Cj);     // apply segment j after current prefix
            EA = f4_mul(Aj, EA);
        }
    }

    // ---- fetch predecessor chunk's carry (warp 0), broadcast via smem ----
    if (seg == 0) {
        float4 P = make_float4(0.f,0.f,0.f,0.f);
        if (p > 0) {
            const int rprev = ((p-1) * nbatch + g) * VG + vg;
            unsigned* f = &g_flag[rprev][lane];
            unsigned v;
            asm volatile("ld.global.acquire.gpu.b32 %0, [%1];"
                         : "=r"(v) : "l"(f) : "memory");
            while (!v) {
                __nanosleep(40);
                asm volatile("ld.global.acquire.gpu.b32 %0, [%1];"
                             : "=r"(v) : "l"(f) : "memory");
            }
            P = g_prefix[rprev][lane];
            // consumer-reset: restore the "flags are zero" invariant for the
            // next graph replay (sole consumer of this flag; ordering across
            // launches is provided by the kernel boundary).
            asm volatile("st.global.relaxed.gpu.b32 [%0], %1;"
                         :: "l"(f), "r"(0u) : "memory");
        }
        sP[lane] = P;
    }
    __syncthreads();

    // full c-prefix at this thread's segment start
    const float4 P  = sP[lane];
    const float4 Pc = f4_fma(EA, P, EC);

    // ---- publish own carry FIRST (shortens the cross-chunk chain) ----
    if (seg == SEGS-1 && p < CH-1) {
        const int rcur = (p * nbatch + g) * VG + vg;
        float4 carry = f4_fma(A[LSEG-1], Pc, C[LSEG-1]);
        g_prefix[rcur][lane] = carry;
        asm volatile("st.global.release.gpu.b32 [%0], %1;"
                     :: "l"(&g_flag[rcur][lane]), "r"(1u) : "memory");
    }

    // ---- finalize + store outputs ----
    #pragma unroll
    for (int i = 0; i < LSEG; ++i) {
        float4 cf = f4_fma(A[i], Pc, C[i]);
        __stcs(po + (size_t)i * OS4, cf);
    }
}

extern "C" void kernel_launch(void* const* d_in, const int* in_sizes, int n_in,
                              void* d_out, int out_size)
{
    const float* in  = (const float*)d_in[0];
    float*       out = (float*)d_out;

    const int batch = in_sizes[0] / (T_C * 2 * UNITS_C);

    const int grid = CH * batch * VG;      // 8192 for B=16
    tempo_scan_kernel<<<grid, 256>>>(in, out, batch);
}